// round 3
// baseline (speedup 1.0000x reference)
#include <cuda_runtime.h>
#include <cstdint>

// Problem constants
#define N_ROWS 16384      // B*H*W
#define DIM    256        // D
#define K_CODES 8192      // codebook entries

// GEMM tiling
#define BM 128
#define BN 128
#define BKD 16
#define KSPLIT 4
#define CODES_PER_BLK (K_CODES / KSPLIT)   // 2048

#define G2_BLOCKS (N_ROWS / 8)             // gather kernel: 8 rows per block -> 2048

// Scratch (no cudaMalloc allowed)
__device__ unsigned long long g_best[N_ROWS];
__device__ float g_zsq[N_ROWS];
__device__ float g_esq[K_CODES];
__device__ float g_partial[G2_BLOCKS];

// ---------------------------------------------------------------------------
// Init: best = +inf key
// ---------------------------------------------------------------------------
__global__ void init_kernel() {
    int i = blockIdx.x * blockDim.x + threadIdx.x;
    if (i < N_ROWS) g_best[i] = 0xFFFFFFFFFFFFFFFFull;
}

// ---------------------------------------------------------------------------
// Row sums of squares for z and codebook (one warp per row)
// ---------------------------------------------------------------------------
__global__ void sq_kernel(const float* __restrict__ z, const float* __restrict__ cb) {
    int warp = (blockIdx.x * blockDim.x + threadIdx.x) >> 5;
    int lane = threadIdx.x & 31;
    if (warp >= N_ROWS + K_CODES) return;
    const float* src = (warp < N_ROWS) ? (z + (size_t)warp * DIM)
                                       : (cb + (size_t)(warp - N_ROWS) * DIM);
    float s = 0.f;
    #pragma unroll
    for (int k = 0; k < DIM; k += 32) {
        float v = src[k + lane];
        s = fmaf(v, v, s);
    }
    #pragma unroll
    for (int o = 16; o > 0; o >>= 1) s += __shfl_xor_sync(0xFFFFFFFFu, s, o);
    if (lane == 0) {
        if (warp < N_ROWS) g_zsq[warp] = s;
        else               g_esq[warp - N_ROWS] = s;
    }
}

// ---------------------------------------------------------------------------
// Fused SGEMM (cross = z @ cb^T) + per-row argmin of (zsq + esq) - 2*cross.
// 128x128 tile, 8x8 per thread, 256 threads. Codes split across blockIdx.y.
// Global merge via atomicMin on (dist_bits << 32 | idx): dists > 0 so float
// bit order == numeric order; ties resolve to the lowest index like argmin.
// ---------------------------------------------------------------------------
__global__ __launch_bounds__(256, 2)
void argmin_gemm_kernel(const float* __restrict__ z, const float* __restrict__ cb) {
    __shared__ float As[BKD][BM];
    __shared__ float Bs[BKD][BN];
    __shared__ float zsq_s[BM];
    __shared__ float esq_s[BN];

    const int tid = threadIdx.x;
    const int tx  = tid & 15;          // code-tile dim (16 threads)
    const int ty  = tid >> 4;          // row-tile dim  (16 threads)
    const int row0  = blockIdx.x * BM;
    const int cbase = blockIdx.y * CODES_PER_BLK;

    if (tid < BM) zsq_s[tid] = g_zsq[row0 + tid];

    float    bestd[8];
    unsigned bestidx[8];
    #pragma unroll
    for (int i = 0; i < 8; i++) { bestd[i] = 3.4e38f; bestidx[i] = 0u; }

    for (int ct = 0; ct < CODES_PER_BLK; ct += BN) {
        const int code0 = cbase + ct;
        __syncthreads();                       // protect esq_s readers of prev tile
        if (tid < BN) esq_s[tid] = g_esq[code0 + tid];

        float acc[8][8];
        #pragma unroll
        for (int i = 0; i < 8; i++)
            #pragma unroll
            for (int j = 0; j < 8; j++) acc[i][j] = 0.f;

        for (int kc = 0; kc < DIM; kc += BKD) {
            __syncthreads();
            // Load A and B chunks (BM x BKD each = 512 float4s, 2 per thread)
            #pragma unroll
            for (int l = 0; l < 2; l++) {
                int id = tid * 2 + l;          // 0..511
                int m  = id >> 2;
                int k4 = (id & 3) * 4;
                float4 va = *reinterpret_cast<const float4*>(
                    z + (size_t)(row0 + m) * DIM + kc + k4);
                As[k4 + 0][m] = va.x; As[k4 + 1][m] = va.y;
                As[k4 + 2][m] = va.z; As[k4 + 3][m] = va.w;
                float4 vb = *reinterpret_cast<const float4*>(
                    cb + (size_t)(code0 + m) * DIM + kc + k4);
                Bs[k4 + 0][m] = vb.x; Bs[k4 + 1][m] = vb.y;
                Bs[k4 + 2][m] = vb.z; Bs[k4 + 3][m] = vb.w;
            }
            __syncthreads();

            #pragma unroll
            for (int kk = 0; kk < BKD; kk++) {
                float a[8], b[8];
                float4 a0 = *reinterpret_cast<const float4*>(&As[kk][ty * 8]);
                float4 a1 = *reinterpret_cast<const float4*>(&As[kk][ty * 8 + 4]);
                a[0]=a0.x; a[1]=a0.y; a[2]=a0.z; a[3]=a0.w;
                a[4]=a1.x; a[5]=a1.y; a[6]=a1.z; a[7]=a1.w;
                float4 b0 = *reinterpret_cast<const float4*>(&Bs[kk][tx * 8]);
                float4 b1 = *reinterpret_cast<const float4*>(&Bs[kk][tx * 8 + 4]);
                b[0]=b0.x; b[1]=b0.y; b[2]=b0.z; b[3]=b0.w;
                b[4]=b1.x; b[5]=b1.y; b[6]=b1.z; b[7]=b1.w;
                #pragma unroll
                for (int i = 0; i < 8; i++)
                    #pragma unroll
                    for (int j = 0; j < 8; j++)
                        acc[i][j] = fmaf(a[i], b[j], acc[i][j]);
            }
        }

        // Epilogue: dist = (zsq + esq) - 2*cross, matching reference op order.
        #pragma unroll
        for (int i = 0; i < 8; i++) {
            float zr = zsq_s[ty * 8 + i];
            #pragma unroll
            for (int j = 0; j < 8; j++) {
                float t = zr + esq_s[tx * 8 + j];
                float d = t - 2.0f * acc[i][j];
                if (d < bestd[i]) {            // strict: earliest index wins
                    bestd[i]   = d;
                    bestidx[i] = (unsigned)(code0 + tx * 8 + j);
                }
            }
        }
    }

    #pragma unroll
    for (int i = 0; i < 8; i++) {
        unsigned long long key =
            ((unsigned long long)__float_as_uint(bestd[i]) << 32) | bestidx[i];
        atomicMin(&g_best[row0 + ty * 8 + i], key);
    }
}

// ---------------------------------------------------------------------------
// Gather: z_q_st = z + (z_q - z); indices as float; per-block partial sums of
// (z - z_q)^2 with a fixed (deterministic) reduction order.
// One warp per row, 8 rows per block.
// ---------------------------------------------------------------------------
__global__ void gather_kernel(const float* __restrict__ z,
                              const float* __restrict__ cb,
                              float* __restrict__ out) {
    __shared__ float wsum[8];
    int warpId = threadIdx.x >> 5;
    int lane   = threadIdx.x & 31;
    int r = blockIdx.x * 8 + warpId;

    unsigned idx = (unsigned)(g_best[r] & 0xFFFFFFFFull);
    const float* zr = z  + (size_t)r * DIM;
    const float* er = cb + (size_t)idx * DIM;
    float* orow = out + (size_t)r * DIM;

    float s = 0.f;
    #pragma unroll
    for (int k = 0; k < DIM; k += 32) {
        float zv = zr[k + lane];
        float ev = er[k + lane];
        orow[k + lane] = zv + (ev - zv);       // straight-through, exact ref ops
        float diff = zv - ev;
        s = fmaf(diff, diff, s);
    }
    #pragma unroll
    for (int o = 16; o > 0; o >>= 1) s += __shfl_xor_sync(0xFFFFFFFFu, s, o);
    if (lane == 0) {
        wsum[warpId] = s;
        out[(size_t)N_ROWS * DIM + r] = (float)idx;   // indices region
    }
    __syncthreads();
    if (threadIdx.x == 0) {
        float t = 0.f;
        #pragma unroll
        for (int w = 0; w < 8; w++) t += wsum[w];     // fixed order
        g_partial[blockIdx.x] = t;
    }
}

// ---------------------------------------------------------------------------
// Final deterministic reduction of partial sums -> vq_loss
// ---------------------------------------------------------------------------
__global__ void loss_kernel(float* __restrict__ out) {
    __shared__ float sm[256];
    int t = threadIdx.x;
    float s = 0.f;
    #pragma unroll
    for (int k = 0; k < G2_BLOCKS; k += 256) s += g_partial[k + t];  // fixed order
    sm[t] = s;
    __syncthreads();
    for (int o = 128; o > 0; o >>= 1) {
        if (t < o) sm[t] = sm[t] + sm[t + o];
        __syncthreads();
    }
    if (t == 0) {
        float m = sm[0] / (float)((size_t)N_ROWS * DIM);  // mean((z - z_q)^2)
        // vq_loss = codebook_loss + 0.25 * commitment_loss, both equal m
        out[(size_t)N_ROWS * DIM + N_ROWS] = m + 0.25f * m;
    }
}

// ---------------------------------------------------------------------------
// Launch
// ---------------------------------------------------------------------------
extern "C" void kernel_launch(void* const* d_in, const int* in_sizes, int n_in,
                              void* d_out, int out_size) {
    const float* z  = (const float*)d_in[0];   // [16,32,32,256] -> [16384,256]
    const float* cb = (const float*)d_in[1];   // [8192,256]
    float* out = (float*)d_out;                // [zq_st | indices | loss]
    (void)in_sizes; (void)n_in; (void)out_size;

    init_kernel<<<(N_ROWS + 255) / 256, 256>>>();

    int sq_warps = N_ROWS + K_CODES;                  // 24576 rows
    sq_kernel<<<(sq_warps * 32 + 255) / 256, 256>>>(z, cb);

    dim3 grid(N_ROWS / BM, KSPLIT);                   // (128, 4)
    argmin_gemm_kernel<<<grid, 256>>>(z, cb);

    gather_kernel<<<G2_BLOCKS, 256>>>(z, cb, out);

    loss_kernel<<<1, 256>>>(out);
}

// round 4
// speedup vs baseline: 3.8773x; 3.8773x over previous
#include <cuda_runtime.h>
#include <cuda_bf16.h>
#include <cstdint>

// Problem constants
#define N_ROWS 16384      // B*H*W
#define DIM    256        // D
#define K_CODES 8192      // codebook entries

#define BM 128            // rows per CTA tile
#define BN 128            // codes per inner tile
#define YSPLIT 8          // code splits across blockIdx.y
#define CODES_PER_Y (K_CODES / YSPLIT)   // 1024 -> 8 inner tiles of 128

#define MARGIN 0.125f     // >= 2 * worst-case bf16 cross error (C-S bound 0.104)
#define CAND_CAP (8u * 1024u * 1024u)    // 8M candidate slots (32MB)

#define G2_BLOCKS (N_ROWS / 8)

// ---------------------------------------------------------------------------
// Device scratch (no cudaMalloc allowed)
// ---------------------------------------------------------------------------
__device__ unsigned long long g_best[N_ROWS];     // packed (exact distbits<<32 | idx)
__device__ unsigned g_rowmin[N_ROWS];             // running approx min (float bits)
__device__ float g_zsq[N_ROWS];
__device__ float g_esq[K_CODES];
__device__ float g_partial[G2_BLOCKS];
__device__ __nv_bfloat16 g_zb[N_ROWS * DIM];      // bf16 copies
__device__ __nv_bfloat16 g_cbb[K_CODES * DIM];
__device__ unsigned g_cand[CAND_CAP];             // packed (row<<13 | code)
__device__ unsigned g_ncand;

// ---------------------------------------------------------------------------
// Init
// ---------------------------------------------------------------------------
__global__ void init_kernel() {
    int i = blockIdx.x * blockDim.x + threadIdx.x;
    if (i < N_ROWS) {
        g_best[i]   = 0xFFFFFFFFFFFFFFFFull;
        g_rowmin[i] = 0xFFFFFFFFu;
    }
    if (i == 0) g_ncand = 0u;
}

// ---------------------------------------------------------------------------
// fp32 -> bf16 conversion of z and codebook (8 elems / thread)
// ---------------------------------------------------------------------------
__device__ __forceinline__ unsigned pack_bf2(float a, float b) {
    __nv_bfloat162 h = __floats2bfloat162_rn(a, b);
    unsigned u;
    memcpy(&u, &h, 4);
    return u;
}

__global__ void convert_kernel(const float* __restrict__ z,
                               const float* __restrict__ cb) {
    const int ZCH = N_ROWS * DIM / 8;          // 524288
    int id = blockIdx.x * blockDim.x + threadIdx.x;
    const float4* src;
    __nv_bfloat16* dst;
    int off;
    if (id < ZCH) { src = (const float4*)z;  dst = g_zb;  off = id; }
    else          { src = (const float4*)cb; dst = g_cbb; off = id - ZCH; }
    float4 a = src[off * 2 + 0];
    float4 b = src[off * 2 + 1];
    uint4 o;
    o.x = pack_bf2(a.x, a.y);
    o.y = pack_bf2(a.z, a.w);
    o.z = pack_bf2(b.x, b.y);
    o.w = pack_bf2(b.z, b.w);
    *reinterpret_cast<uint4*>(dst + (size_t)off * 8) = o;
}

// ---------------------------------------------------------------------------
// Row sums of squares (fp32, one warp per row) — also used by re-rank
// ---------------------------------------------------------------------------
__global__ void sq_kernel(const float* __restrict__ z, const float* __restrict__ cb) {
    int warp = (blockIdx.x * blockDim.x + threadIdx.x) >> 5;
    int lane = threadIdx.x & 31;
    if (warp >= N_ROWS + K_CODES) return;
    const float* src = (warp < N_ROWS) ? (z + (size_t)warp * DIM)
                                       : (cb + (size_t)(warp - N_ROWS) * DIM);
    float s = 0.f;
    #pragma unroll
    for (int k = 0; k < DIM; k += 32) {
        float v = src[k + lane];
        s = fmaf(v, v, s);
    }
    #pragma unroll
    for (int o = 16; o > 0; o >>= 1) s += __shfl_xor_sync(0xFFFFFFFFu, s, o);
    if (lane == 0) {
        if (warp < N_ROWS) g_zsq[warp] = s;
        else               g_esq[warp - N_ROWS] = s;
    }
}

// ---------------------------------------------------------------------------
// PTX helpers
// ---------------------------------------------------------------------------
__device__ __forceinline__ void ldsm_x4(unsigned* r, unsigned addr) {
    asm volatile("ldmatrix.sync.aligned.m8n8.x4.shared.b16 {%0,%1,%2,%3}, [%4];"
                 : "=r"(r[0]), "=r"(r[1]), "=r"(r[2]), "=r"(r[3]) : "r"(addr));
}
__device__ __forceinline__ void ldsm_x2(unsigned* r, unsigned addr) {
    asm volatile("ldmatrix.sync.aligned.m8n8.x2.shared.b16 {%0,%1}, [%2];"
                 : "=r"(r[0]), "=r"(r[1]) : "r"(addr));
}
__device__ __forceinline__ void mma_bf16(float* c, const unsigned* a, const unsigned* b) {
    asm volatile(
        "mma.sync.aligned.m16n8k16.row.col.f32.bf16.bf16.f32 "
        "{%0,%1,%2,%3}, {%4,%5,%6,%7}, {%8,%9}, {%0,%1,%2,%3};"
        : "+f"(c[0]), "+f"(c[1]), "+f"(c[2]), "+f"(c[3])
        : "r"(a[0]), "r"(a[1]), "r"(a[2]), "r"(a[3]), "r"(b[0]), "r"(b[1]));
}

// ---------------------------------------------------------------------------
// Approx bf16 GEMM + running-min filter + candidate append.
// CTA: 128 rows x (8 tiles of 128 codes), full K=256 resident in smem.
// 8 warps: warp w -> m-offset 32*(w&3), n-offset 64*(w>>2). Warp tile 32x64.
// SMEM swizzle: 16B granule g at row r stored at granule (g ^ (r&7)).
// ---------------------------------------------------------------------------
extern __shared__ char smem_raw[];

__global__ __launch_bounds__(256, 1)
void approx_gemm_kernel() {
    __nv_bfloat16* As = (__nv_bfloat16*)smem_raw;              // 128*256 bf16 = 64KB
    __nv_bfloat16* Bs = As + BM * DIM;                         // 64KB
    float*    zsq_s    = (float*)(Bs + BN * DIM);
    float*    esq_s    = zsq_s + BM;
    unsigned* rowmin_s = (unsigned*)(esq_s + BN);
    float*    cut_s    = (float*)(rowmin_s + BM);

    const int tid  = threadIdx.x;
    const int lane = tid & 31;
    const int warp = tid >> 5;
    const int wm = (warp & 3) * 32;     // warp m offset
    const int wn = (warp >> 2) * 64;    // warp n offset
    const int row0 = blockIdx.x * BM;

    // Load A tile (all K) with swizzle
    #pragma unroll
    for (int i = 0; i < 16; i++) {
        int id = i * 256 + tid;
        int r = id >> 5, g = id & 31;
        uint4 v = *reinterpret_cast<const uint4*>(g_zb + ((size_t)(row0 + r) << 8) + g * 8);
        *reinterpret_cast<uint4*>(As + r * DIM + ((g ^ (r & 7)) << 3)) = v;
    }
    if (tid < BM) zsq_s[tid] = g_zsq[row0 + tid];

    unsigned a_base = (unsigned)__cvta_generic_to_shared(As);
    unsigned b_base = (unsigned)__cvta_generic_to_shared(Bs);

    // Precompute ldmatrix addresses (k-step varies by +32B per step)
    // A: lanes: row = wm + mt*16 + (lane&15), gran = ks*2 + (lane>>4)
    // B: lanes: row = wn + nt*8  + (lane&7),  gran = ks*2 + ((lane>>3)&1)
    const int a_r[2] = { wm + (lane & 15), wm + 16 + (lane & 15) };
    const int b_r0 = wn + (lane & 7);
    const int a_g0 = (lane >> 4);
    const int b_g0 = ((lane >> 3) & 1);

    for (int ct = 0; ct < 8; ct++) {
        const int c0 = blockIdx.y * CODES_PER_Y + ct * BN;
        __syncthreads();   // prior tile fully consumed
        #pragma unroll
        for (int i = 0; i < 16; i++) {
            int id = i * 256 + tid;
            int r = id >> 5, g = id & 31;
            uint4 v = *reinterpret_cast<const uint4*>(g_cbb + ((size_t)(c0 + r) << 8) + g * 8);
            *reinterpret_cast<uint4*>(Bs + r * DIM + ((g ^ (r & 7)) << 3)) = v;
        }
        if (tid < BN) { esq_s[tid] = g_esq[c0 + tid]; rowmin_s[tid] = 0xFFFFFFFFu; }
        __syncthreads();

        float acc[2][8][4];
        #pragma unroll
        for (int mt = 0; mt < 2; mt++)
            #pragma unroll
            for (int nt = 0; nt < 8; nt++)
                #pragma unroll
                for (int q = 0; q < 4; q++) acc[mt][nt][q] = 0.f;

        #pragma unroll
        for (int ks = 0; ks < 16; ks++) {
            unsigned a[2][4], b[8][2];
            #pragma unroll
            for (int mt = 0; mt < 2; mt++) {
                int r = a_r[mt];
                int g = ks * 2 + a_g0;
                ldsm_x4(a[mt], a_base + (unsigned)((r * DIM + ((g ^ (r & 7)) << 3)) * 2));
            }
            #pragma unroll
            for (int nt = 0; nt < 8; nt++) {
                int r = b_r0 + nt * 8;
                int g = ks * 2 + b_g0;
                ldsm_x2(b[nt], b_base + (unsigned)((r * DIM + ((g ^ (r & 7)) << 3)) * 2));
            }
            #pragma unroll
            for (int mt = 0; mt < 2; mt++)
                #pragma unroll
                for (int nt = 0; nt < 8; nt++)
                    mma_bf16(acc[mt][nt], a[mt], b[nt]);
        }

        // ---- Epilogue phase 1: per-row running min ----
        // acc[mt][nt][fr*2+c] -> row = wm + mt*16 + (lane>>2) + fr*8
        //                        col = wn + nt*8 + 2*(lane&3) + c
        #pragma unroll
        for (int mt = 0; mt < 2; mt++) {
            #pragma unroll
            for (int fr = 0; fr < 2; fr++) {
                int rl = wm + mt * 16 + (lane >> 2) + fr * 8;
                float zr = zsq_s[rl];
                float mn = 3.4e38f;
                #pragma unroll
                for (int nt = 0; nt < 8; nt++) {
                    #pragma unroll
                    for (int c = 0; c < 2; c++) {
                        int cl = wn + nt * 8 + 2 * (lane & 3) + c;
                        float d = (zr + esq_s[cl]) - 2.0f * acc[mt][nt][fr * 2 + c];
                        mn = fminf(mn, d);
                    }
                }
                atomicMin(&rowmin_s[rl], __float_as_uint(mn));
            }
        }
        __syncthreads();
        if (tid < BM) {
            unsigned mine = rowmin_s[tid];
            unsigned old  = atomicMin(&g_rowmin[row0 + tid], mine);
            unsigned cur  = (old < mine) ? old : mine;
            cut_s[tid] = __uint_as_float(cur) + MARGIN;
        }
        __syncthreads();

        // ---- Epilogue phase 2: append candidates within margin ----
        #pragma unroll
        for (int mt = 0; mt < 2; mt++) {
            #pragma unroll
            for (int fr = 0; fr < 2; fr++) {
                int rl = wm + mt * 16 + (lane >> 2) + fr * 8;
                float zr  = zsq_s[rl];
                float cut = cut_s[rl];
                #pragma unroll
                for (int nt = 0; nt < 8; nt++) {
                    #pragma unroll
                    for (int c = 0; c < 2; c++) {
                        int cl = wn + nt * 8 + 2 * (lane & 3) + c;
                        float d = (zr + esq_s[cl]) - 2.0f * acc[mt][nt][fr * 2 + c];
                        if (d <= cut) {
                            unsigned pos = atomicAdd(&g_ncand, 1u);
                            if (pos < CAND_CAP)
                                g_cand[pos] = ((unsigned)(row0 + rl) << 13) | (unsigned)(c0 + cl);
                        }
                    }
                }
            }
        }
    }
}

// ---------------------------------------------------------------------------
// Exact fp32 re-rank of candidates. Sequential fmaf chain in k-order and
// (zsq + esq) - 2*dot epilogue: bit-identical dists to the round-3 kernel.
// Winner per row via order-independent u64 atomicMin (ties -> lowest index).
// ---------------------------------------------------------------------------
__global__ void rerank_kernel(const float* __restrict__ z, const float* __restrict__ cb) {
    unsigned n = g_ncand;
    if (n > CAND_CAP) n = CAND_CAP;
    unsigned stride = gridDim.x * blockDim.x;
    for (unsigned e = blockIdx.x * blockDim.x + threadIdx.x; e < n; e += stride) {
        unsigned ent = g_cand[e];
        unsigned r = ent >> 13;
        unsigned j = ent & 8191u;
        const float4* zr = reinterpret_cast<const float4*>(z  + (size_t)r * DIM);
        const float4* cr = reinterpret_cast<const float4*>(cb + (size_t)j * DIM);
        float s = 0.f;
        #pragma unroll 8
        for (int k = 0; k < 64; k++) {
            float4 a = zr[k];
            float4 b = cr[k];
            s = fmaf(a.x, b.x, s);
            s = fmaf(a.y, b.y, s);
            s = fmaf(a.z, b.z, s);
            s = fmaf(a.w, b.w, s);
        }
        float t = g_zsq[r] + g_esq[j];
        float d = t - 2.0f * s;
        unsigned long long key =
            ((unsigned long long)__float_as_uint(d) << 32) | (unsigned long long)j;
        atomicMin(&g_best[r], key);
    }
}

// ---------------------------------------------------------------------------
// Gather z_q_st, indices, and deterministic partial loss sums
// ---------------------------------------------------------------------------
__global__ void gather_kernel(const float* __restrict__ z,
                              const float* __restrict__ cb,
                              float* __restrict__ out) {
    __shared__ float wsum[8];
    int warpId = threadIdx.x >> 5;
    int lane   = threadIdx.x & 31;
    int r = blockIdx.x * 8 + warpId;

    unsigned idx = (unsigned)(g_best[r] & 0xFFFFFFFFull);
    const float* zr = z  + (size_t)r * DIM;
    const float* er = cb + (size_t)idx * DIM;
    float* orow = out + (size_t)r * DIM;

    float s = 0.f;
    #pragma unroll
    for (int k = 0; k < DIM; k += 32) {
        float zv = zr[k + lane];
        float ev = er[k + lane];
        orow[k + lane] = zv + (ev - zv);
        float diff = zv - ev;
        s = fmaf(diff, diff, s);
    }
    #pragma unroll
    for (int o = 16; o > 0; o >>= 1) s += __shfl_xor_sync(0xFFFFFFFFu, s, o);
    if (lane == 0) {
        wsum[warpId] = s;
        out[(size_t)N_ROWS * DIM + r] = (float)idx;
    }
    __syncthreads();
    if (threadIdx.x == 0) {
        float t = 0.f;
        #pragma unroll
        for (int w = 0; w < 8; w++) t += wsum[w];
        g_partial[blockIdx.x] = t;
    }
}

__global__ void loss_kernel(float* __restrict__ out) {
    __shared__ float sm[256];
    int t = threadIdx.x;
    float s = 0.f;
    #pragma unroll
    for (int k = 0; k < G2_BLOCKS; k += 256) s += g_partial[k + t];
    sm[t] = s;
    __syncthreads();
    for (int o = 128; o > 0; o >>= 1) {
        if (t < o) sm[t] = sm[t] + sm[t + o];
        __syncthreads();
    }
    if (t == 0) {
        float m = sm[0] / (float)((size_t)N_ROWS * DIM);
        out[(size_t)N_ROWS * DIM + N_ROWS] = m + 0.25f * m;
    }
}

// ---------------------------------------------------------------------------
// Launch
// ---------------------------------------------------------------------------
extern "C" void kernel_launch(void* const* d_in, const int* in_sizes, int n_in,
                              void* d_out, int out_size) {
    const float* z  = (const float*)d_in[0];
    const float* cb = (const float*)d_in[1];
    float* out = (float*)d_out;
    (void)in_sizes; (void)n_in; (void)out_size;

    const int SMEM_BYTES = BM * DIM * 2 + BN * DIM * 2 + (BM + BN + BM + BM) * 4;
    cudaFuncSetAttribute(approx_gemm_kernel,
                         cudaFuncAttributeMaxDynamicSharedMemorySize, SMEM_BYTES);

    init_kernel<<<(N_ROWS + 255) / 256, 256>>>();

    // 786432 chunks of 8 elements
    convert_kernel<<<3072, 256>>>(z, cb);

    int sq_warps = N_ROWS + K_CODES;
    sq_kernel<<<(sq_warps * 32 + 255) / 256, 256>>>(z, cb);

    dim3 grid(N_ROWS / BM, YSPLIT);          // (128, 8)
    approx_gemm_kernel<<<grid, 256, SMEM_BYTES>>>();

    rerank_kernel<<<1024, 256>>>(z, cb);

    gather_kernel<<<G2_BLOCKS, 256>>>(z, cb, out);

    loss_kernel<<<1, 256>>>(out);
}